// round 8
// baseline (speedup 1.0000x reference)
#include <cuda_runtime.h>
#include <cstdint>

// out[i, :] = embedding[index[i], :],  U=1M rows, D=64 f32 (256B/row), N=2M.
//
// Partition-then-gather with ORDER-PRESERVING partition:
//   K1 count:   per-block bucket histograms (register counts + redux).
//   K2 scan:    one block scans 1024 int4 block-counts -> exact global base
//               per (block, bucket) + bucket segment offsets.
//   K3 scatter: (orig_pos, index) pairs into flat scratch at scanned bases;
//               within a block, positions from smem atomics (order scrambled
//               only inside a ~128KB output window -> row-buffer friendly).
//   4 dense gather passes over bucket segments; each pass's 64MB table slice
//   stays L2-resident, and output writes are now block-ordered (monotone),
//   restoring DRAM write locality that round-7's unsorted buckets lost.

static constexpr int D = 64;
static constexpr int VEC_PER_ROW = D / 4;   // 16
static constexpr int UNROLL = 4;
static constexpr int P = 4;
static constexpr int N_MAX = 1 << 21;       // 2M lookups
static constexpr int PT = 256;              // partition threads
static constexpr int IPT = 8;               // items per thread
static constexpr int ITEMS = PT * IPT;      // 2048 per block
static constexpr int MAX_PBLK = 1024;       // max partition blocks (scan width)

__device__ int4 g_blkcnt[MAX_PBLK];
__device__ int4 g_base[MAX_PBLK];
__device__ int  g_boff[P];
__device__ int  g_bcnt[P];
__device__ int2 g_pairs[N_MAX];

// ------------------------------------------------------------------ K1
__global__ __launch_bounds__(PT) void count_kernel(
    const int* __restrict__ idx, int n, int shift)
{
    __shared__ int s_cnt[P];
    const int tid = threadIdx.x;
    const int lane = tid & 31;
    if (tid < P) s_cnt[tid] = 0;
    __syncthreads();

    const int base = blockIdx.x * ITEMS;
    int c[P] = {0, 0, 0, 0};
#pragma unroll
    for (int j = 0; j < IPT; j++) {
        int i = base + j * PT + tid;
        if (i < n) {
            int b = __ldg(&idx[i]) >> shift;
            c[0] += (b == 0); c[1] += (b == 1);
            c[2] += (b == 2); c[3] += (b == 3);
        }
    }
#pragma unroll
    for (int k = 0; k < P; k++) {
        int w = __reduce_add_sync(0xffffffffu, c[k]);
        if (lane == 0) atomicAdd(&s_cnt[k], w);
    }
    __syncthreads();
    if (tid == 0)
        g_blkcnt[blockIdx.x] = make_int4(s_cnt[0], s_cnt[1], s_cnt[2], s_cnt[3]);
}

// ------------------------------------------------------------------ K2
__global__ __launch_bounds__(1024) void scan_kernel(int nb)
{
    __shared__ int4 s[1024];
    const int t = threadIdx.x;
    int4 v = (t < nb) ? g_blkcnt[t] : make_int4(0, 0, 0, 0);
    int4 inc = v;
    s[t] = inc;
    __syncthreads();
    for (int off = 1; off < 1024; off <<= 1) {
        int4 add = (t >= off) ? s[t - off] : make_int4(0, 0, 0, 0);
        __syncthreads();
        inc.x += add.x; inc.y += add.y; inc.z += add.z; inc.w += add.w;
        s[t] = inc;
        __syncthreads();
    }
    int4 tot = s[1023];
    int off0 = 0, off1 = tot.x, off2 = off1 + tot.y, off3 = off2 + tot.z;
    if (t < nb) {
        g_base[t] = make_int4(off0 + inc.x - v.x, off1 + inc.y - v.y,
                              off2 + inc.z - v.z, off3 + inc.w - v.w);
    }
    if (t == 0) {
        g_boff[0] = off0; g_boff[1] = off1; g_boff[2] = off2; g_boff[3] = off3;
        g_bcnt[0] = tot.x; g_bcnt[1] = tot.y; g_bcnt[2] = tot.z; g_bcnt[3] = tot.w;
    }
}

// ------------------------------------------------------------------ K3
__global__ __launch_bounds__(PT) void scatter_kernel(
    const int* __restrict__ idx, int n, int shift)
{
    __shared__ int s_cur[P];
    const int tid = threadIdx.x;
    if (tid < P) {
        const int* b = (const int*)&g_base[blockIdx.x];
        s_cur[tid] = b[tid];
    }
    __syncthreads();

    const int base = blockIdx.x * ITEMS;
#pragma unroll
    for (int j = 0; j < IPT; j++) {
        int i = base + j * PT + tid;
        if (i < n) {
            int v = __ldg(&idx[i]);
            int b = v >> shift;
            int pos = atomicAdd(&s_cur[b], 1);
            g_pairs[pos] = make_int2(i, v);
        }
    }
}

// -------------------------------------------------------------- gather
__global__ __launch_bounds__(256) void gather_bucket_kernel(
    const float4* __restrict__ emb,
    float4*       __restrict__ out,
    int pass)
{
    const int seg = g_boff[pass];
    const int n_p = g_bcnt[pass];
    const int64_t n_vec = (int64_t)n_p * VEC_PER_ROW;
    const int2* __restrict__ pairs = g_pairs + seg;

    const int64_t stride = (int64_t)gridDim.x * blockDim.x;
    int64_t g = (int64_t)blockIdx.x * blockDim.x + threadIdx.x;

    while (g + (UNROLL - 1) * stride < n_vec) {
        int64_t gg[UNROLL];
        int2    pr[UNROLL];
#pragma unroll
        for (int u = 0; u < UNROLL; u++) {
            gg[u] = g + u * stride;
            pr[u] = __ldg(&pairs[gg[u] >> 4]);
        }
        float4 v[UNROLL];
#pragma unroll
        for (int u = 0; u < UNROLL; u++) {
            int sg = (int)(gg[u] & 15);
            v[u] = __ldg(&emb[(int64_t)pr[u].y * VEC_PER_ROW + sg]);
        }
#pragma unroll
        for (int u = 0; u < UNROLL; u++) {
            int sg = (int)(gg[u] & 15);
            __stcs(&out[(int64_t)pr[u].x * VEC_PER_ROW + sg], v[u]);
        }
        g += UNROLL * stride;
    }
    while (g < n_vec) {
        int2 pr = __ldg(&pairs[g >> 4]);
        int sg = (int)(g & 15);
        float4 v = __ldg(&emb[(int64_t)pr.y * VEC_PER_ROW + sg]);
        __stcs(&out[(int64_t)pr.x * VEC_PER_ROW + sg], v);
        g += stride;
    }
}

// ------------------------------------------------------ fallback plain
__global__ __launch_bounds__(256) void gather_plain_kernel(
    const float4* __restrict__ emb,
    const int*    __restrict__ idx,
    float4*       __restrict__ out,
    int64_t n_vec)
{
    const int64_t stride = (int64_t)gridDim.x * blockDim.x;
    int64_t g = (int64_t)blockIdx.x * blockDim.x + threadIdx.x;
    while (g + (UNROLL - 1) * stride < n_vec) {
        int64_t gg[UNROLL];
        int     src[UNROLL];
#pragma unroll
        for (int u = 0; u < UNROLL; u++) {
            gg[u] = g + u * stride;
            src[u] = __ldg(&idx[gg[u] >> 4]);
        }
        float4 v[UNROLL];
#pragma unroll
        for (int u = 0; u < UNROLL; u++) {
            int sg = (int)(gg[u] & 15);
            v[u] = __ldg(&emb[(int64_t)src[u] * VEC_PER_ROW + sg]);
        }
#pragma unroll
        for (int u = 0; u < UNROLL; u++) __stcs(&out[gg[u]], v[u]);
        g += UNROLL * stride;
    }
    while (g < n_vec) {
        int src = __ldg(&idx[g >> 4]);
        int sg = (int)(g & 15);
        float4 v = __ldg(&emb[(int64_t)src * VEC_PER_ROW + sg]);
        __stcs(&out[g], v);
        g += stride;
    }
}

extern "C" void kernel_launch(void* const* d_in, const int* in_sizes, int n_in,
                              void* d_out, int out_size) {
    const float4* emb = (const float4*)d_in[0];  // embedding [U, 64] f32
    const int*    idx = (const int*)d_in[1];     // index [N] i32
    float4*       out = (float4*)d_out;

    int64_t n_emb = in_sizes[0];
    int     U     = (int)(n_emb / D);            // 1048576
    int64_t n     = in_sizes[1];                 // 2097152
    int64_t n_vec = n * VEC_PER_ROW;

    const int threads = 256;
    int part_blocks = (int)((n + ITEMS - 1) / ITEMS);
    bool ok = (U > 0) && ((U & (U - 1)) == 0) && (U % P == 0) &&
              (n <= N_MAX) && (part_blocks <= MAX_PBLK);

    if (!ok) {
        int64_t blocks = (n_vec + (int64_t)threads * UNROLL - 1) /
                         ((int64_t)threads * UNROLL);
        gather_plain_kernel<<<(unsigned)blocks, threads>>>(emb, idx, out, n_vec);
        return;
    }

    int chunk = U / P;
    int shift = 0;
    while ((1 << shift) < chunk) shift++;        // 18 for U=1M

    count_kernel<<<part_blocks, PT>>>(idx, (int)n, shift);
    scan_kernel<<<1, 1024>>>(part_blocks);
    scatter_kernel<<<part_blocks, PT>>>(idx, (int)n, shift);

    int64_t vec_per_pass = (n / P) * VEC_PER_ROW;
    int64_t gblocks = (vec_per_pass + (int64_t)threads * UNROLL - 1) /
                      ((int64_t)threads * UNROLL);   // 8192
    for (int p = 0; p < P; p++) {
        gather_bucket_kernel<<<(unsigned)gblocks, threads>>>(emb, out, p);
    }
}

// round 9
// speedup vs baseline: 1.1771x; 1.1771x over previous
#include <cuda_runtime.h>
#include <cstdint>

// out[i, :] = embedding[index[i], :],  U=1M rows, D=64 f32 (256B/row), N=2M.
// Plain single-sweep gather (the partition variants lost to it twice).
// 8 threads per row, 32B (v8.b32) per thread; UNROLL=4 front-batched
// independent gathers -> 128B of gather data in flight per thread.
// Output = two __stcs float4 per 32B chunk (write-once stream, evict-first).

static constexpr int UNROLL = 4;

__device__ __forceinline__ void ldg256(const unsigned* p, unsigned v[8]) {
    asm("ld.global.nc.v8.b32 {%0,%1,%2,%3,%4,%5,%6,%7}, [%8];"
        : "=r"(v[0]), "=r"(v[1]), "=r"(v[2]), "=r"(v[3]),
          "=r"(v[4]), "=r"(v[5]), "=r"(v[6]), "=r"(v[7])
        : "l"(p));
}

__global__ __launch_bounds__(256) void gather_kernel(
    const unsigned* __restrict__ emb,   // [U * 64] f32 as u32
    const int*      __restrict__ idx,   // [N]
    float4*         __restrict__ out,   // [N * 16] float4
    int n_oct)                          // N * 8 (32B units)
{
    const int stride = gridDim.x * blockDim.x;
    int g = blockIdx.x * blockDim.x + threadIdx.x;

    while (g + (UNROLL - 1) * stride < n_oct) {
        int gg[UNROLL], src[UNROLL];
#pragma unroll
        for (int u = 0; u < UNROLL; u++) {
            gg[u] = g + u * stride;
            src[u] = __ldg(&idx[gg[u] >> 3]);
        }
        unsigned v[UNROLL][8];
#pragma unroll
        for (int u = 0; u < UNROLL; u++) {
            int seg = gg[u] & 7;
            const unsigned* p = emb + (((int64_t)src[u]) << 6) + (seg << 3);
            ldg256(p, v[u]);
        }
#pragma unroll
        for (int u = 0; u < UNROLL; u++) {
            int64_t o = (int64_t)gg[u] * 2;
            float4 a = make_float4(__uint_as_float(v[u][0]), __uint_as_float(v[u][1]),
                                   __uint_as_float(v[u][2]), __uint_as_float(v[u][3]));
            float4 b = make_float4(__uint_as_float(v[u][4]), __uint_as_float(v[u][5]),
                                   __uint_as_float(v[u][6]), __uint_as_float(v[u][7]));
            __stcs(&out[o],     a);
            __stcs(&out[o + 1], b);
        }
        g += UNROLL * stride;
    }
    while (g < n_oct) {
        int src = __ldg(&idx[g >> 3]);
        int seg = g & 7;
        unsigned v[8];
        ldg256(emb + (((int64_t)src) << 6) + (seg << 3), v);
        int64_t o = (int64_t)g * 2;
        float4 a = make_float4(__uint_as_float(v[0]), __uint_as_float(v[1]),
                               __uint_as_float(v[2]), __uint_as_float(v[3]));
        float4 b = make_float4(__uint_as_float(v[4]), __uint_as_float(v[5]),
                               __uint_as_float(v[6]), __uint_as_float(v[7]));
        __stcs(&out[o],     a);
        __stcs(&out[o + 1], b);
        g += stride;
    }
}

extern "C" void kernel_launch(void* const* d_in, const int* in_sizes, int n_in,
                              void* d_out, int out_size) {
    const unsigned* emb = (const unsigned*)d_in[0];  // embedding [U, 64] f32
    const int*      idx = (const int*)d_in[1];       // index [N] i32
    float4*         out = (float4*)d_out;

    int64_t n = in_sizes[1];             // N = 2097152
    int n_oct = (int)(n * 8);            // 16,777,216 32B-chunks

    const int threads = 256;
    int blocks = (n_oct + threads * UNROLL - 1) / (threads * UNROLL);  // 16384
    gather_kernel<<<blocks, threads>>>(emb, idx, out, n_oct);
}

// round 11
// speedup vs baseline: 1.2337x; 1.0481x over previous
#include <cuda_runtime.h>
#include <cstdint>

// out[i, :] = embedding[index[i], :],  U=1M rows, D=64 f32 (256B/row), N=2M.
// Best-known shape: 16 threads/row, one float4 each (row = 2 full 128B lines),
// UNROLL=4 front-batched independent gathers (MLP saturated), exact grid
// mapping (straight-line body, no loop/tail).
//   emb : ld.global.cg  (L2-only; random never-reused lines skip L1)
//   idx : __ldg         (L1; 16-lane broadcast of the same word)
//   out : __stcs        (evict-first streaming write)

static constexpr int UNROLL = 4;

__device__ __forceinline__ float4 ldcg4(const float4* p) {
    float4 v;
    asm("ld.global.cg.v4.f32 {%0,%1,%2,%3}, [%4];"
        : "=f"(v.x), "=f"(v.y), "=f"(v.z), "=f"(v.w)
        : "l"(p));
    return v;
}

__global__ __launch_bounds__(256) void gather_kernel(
    const float4* __restrict__ emb,   // [U * 16] float4
    const int*    __restrict__ idx,   // [N]
    float4*       __restrict__ out,   // [N * 16] float4
    unsigned n_vec)                   // N * 16 = 2^25
{
    const unsigned stride = gridDim.x * blockDim.x;          // n_vec / 4
    const unsigned g0 = blockIdx.x * blockDim.x + threadIdx.x;

    if (g0 + 3u * stride < n_vec) {
        // Exact-cover fast path: straight-line 4 gathers.
        unsigned gg[UNROLL];
        int      src[UNROLL];
#pragma unroll
        for (int u = 0; u < UNROLL; u++) {
            gg[u] = g0 + u * stride;
            src[u] = __ldg(&idx[gg[u] >> 4]);
        }
        float4 v[UNROLL];
#pragma unroll
        for (int u = 0; u < UNROLL; u++) {
            unsigned seg = gg[u] & 15u;
            v[u] = ldcg4(&emb[((int64_t)src[u] << 4) + seg]);
        }
#pragma unroll
        for (int u = 0; u < UNROLL; u++) {
            __stcs(&out[gg[u]], v[u]);
        }
    } else {
        // Generic tail (only taken if sizes aren't the expected exact fit).
        for (unsigned g = g0; g < n_vec; g += stride) {
            int src = __ldg(&idx[g >> 4]);
            unsigned seg = g & 15u;
            float4 v = ldcg4(&emb[((int64_t)src << 4) + seg]);
            __stcs(&out[g], v);
        }
    }
}

extern "C" void kernel_launch(void* const* d_in, const int* in_sizes, int n_in,
                              void* d_out, int out_size) {
    const float4* emb = (const float4*)d_in[0];  // embedding [U, 64] f32
    const int*    idx = (const int*)d_in[1];     // index [N] i32
    float4*       out = (float4*)d_out;

    int64_t n = in_sizes[1];                     // N = 2097152
    unsigned n_vec = (unsigned)(n * 16);         // 33,554,432

    const int threads = 256;
    unsigned blocks = (n_vec + threads * UNROLL - 1) / (threads * UNROLL); // 32768
    gather_kernel<<<blocks, threads>>>(emb, idx, out, n_vec);
}